// round 1
// baseline (speedup 1.0000x reference)
#include <cuda_runtime.h>

// Problem constants (fixed by setup_inputs)
#define GN    6
#define NN    36          // 6*6 occupancy bins
#define NPED  8192
#define HID   128
#define RPB   256         // rows per block, phase 1
#define NSL   16          // j-slices
#define JCH   (NPED / NSL) // 512 j's per block

// Partial counts scratch: [slice][bin][row], fully overwritten every launch.
__device__ float g_pcnt[NSL * NN * NPED];

// ---------------------------------------------------------------------------
// Phase 1: per-row occupancy histogram over a j-slice.
// One thread = one row i. Counters in smem, bin-major so thread t always
// hits bank t%32 (conflict-free). Points for the slice staged in smem and
// read as warp-uniform broadcasts.
// ---------------------------------------------------------------------------
__global__ __launch_bounds__(RPB) void count_kernel(const float* __restrict__ obs2) {
    __shared__ unsigned cnt[NN][RPB];   // 36 KB
    __shared__ float2   pts[JCH];       // 4 KB

    const int t  = threadIdx.x;
    const int i  = blockIdx.x * RPB + t;
    const int j0 = blockIdx.y * JCH;

    const float2* o2 = (const float2*)obs2;

    for (int k = t; k < JCH; k += RPB) pts[k] = o2[j0 + k];
#pragma unroll
    for (int c = 0; c < NN; c++) cnt[c][t] = 0u;

    const float2 pi = o2[i];
    __syncthreads();

    const float xi = pi.x, yi = pi.y;

#pragma unroll 8
    for (int k = 0; k < JCH; k++) {
        const float2 pj = pts[k];                 // warp-uniform broadcast LDS
        // EXACT reference arithmetic: (obs2[j] - obs2[i]) + 3.0f, fp32
        const float dx = (pj.x - xi) + 3.0f;
        const float dy = (pj.y - yi) + 3.0f;
        const int u = __float2int_rd(dx);         // floor; <0 -> huge unsigned
        const int v = __float2int_rd(dy);
        if ((unsigned)u < 6u && (unsigned)v < 6u)
            cnt[u * GN + v][t] += 1u;             // conflict-free RMW
    }
    // No sync needed: each thread only ever touched its own counter column.

    // Self pair (dx=dy=3.0 exactly) always lands in bin 21; remove it once.
    const unsigned self = (i >= j0 && i < j0 + JCH) ? 1u : 0u;

    // Coalesced flush: lane t -> consecutive rows within [slice][bin][*]
    float* dst = &g_pcnt[(blockIdx.y * NN) * NPED + i];
#pragma unroll
    for (int c = 0; c < NN; c++) {
        const unsigned vc = cnt[c][t] - ((c == 3 * GN + 3) ? self : 0u);
        dst[c * NPED] = (float)vc;
    }
}

// ---------------------------------------------------------------------------
// Phase 2: reduce the NSL partial grids and apply the linear embedding.
// Block = 32 rows x 128 hidden. W staged in smem transposed [c][h] so the
// per-h loads are conflict-free; counts read as warp-uniform broadcasts.
// ---------------------------------------------------------------------------
#define P2R 32
__global__ __launch_bounds__(256) void embed_kernel(const float* __restrict__ W,
                                                    const float* __restrict__ b,
                                                    float* __restrict__ out) {
    __shared__ float Ws[NN][HID];   // 18 KB, Ws[c][h] = W[h*NN + c]
    __shared__ float bs[HID];
    __shared__ float cs[P2R][NN];   // reduced counts for this block's rows

    const int t  = threadIdx.x;
    const int i0 = blockIdx.x * P2R;

    for (int idx = t; idx < HID * NN; idx += 256)
        Ws[idx % NN][idx / NN] = W[idx];
    if (t < HID) bs[t] = b[t];

    // Reduce NSL partials: lanes cover consecutive rows -> coalesced LDG.
    for (int idx = t; idx < P2R * NN; idx += 256) {
        const int c = idx >> 5;     // 0..35
        const int r = idx & 31;     // 0..31
        float s = 0.f;
        const float* p = &g_pcnt[c * NPED + i0 + r];
#pragma unroll
        for (int sl = 0; sl < NSL; sl++) s += p[sl * NN * NPED];
        cs[r][c] = s;
    }
    __syncthreads();

    const int h     = t & (HID - 1);
    const int rbase = (t >> 7) * (P2R / 2);

    float w[NN];
#pragma unroll
    for (int c = 0; c < NN; c++) w[c] = Ws[c][h];   // conflict-free (bank = h%32)
    const float bh = bs[h];

#pragma unroll
    for (int r = 0; r < P2R / 2; r++) {
        float acc = bh;
#pragma unroll
        for (int c = 0; c < NN; c++)
            acc = fmaf(cs[rbase + r][c], w[c], acc); // cs is warp-uniform broadcast
        out[(i0 + rbase + r) * HID + h] = acc;
    }
}

// ---------------------------------------------------------------------------
// Inputs (metadata order): 0 hidden_state (unused), 1 obs1 (unused),
// 2 obs2 [8192,2], 3 W [128,36], 4 b [128]. Output fp32 [8192,128].
// ---------------------------------------------------------------------------
extern "C" void kernel_launch(void* const* d_in, const int* in_sizes, int n_in,
                              void* d_out, int out_size) {
    const float* obs2 = (const float*)d_in[2];
    const float* W    = (const float*)d_in[3];
    const float* b    = (const float*)d_in[4];
    float*       out  = (float*)d_out;

    dim3 g1(NPED / RPB, NSL);            // 32 x 16 = 512 blocks
    count_kernel<<<g1, RPB>>>(obs2);
    embed_kernel<<<NPED / P2R, 256>>>(W, b, out);
}

// round 2
// speedup vs baseline: 1.0364x; 1.0364x over previous
#include <cuda_runtime.h>

#define GN    6
#define NN    36
#define NPED  8192
#define HID   128
#define RPB   128          // rows per count block
#define NSL   16           // j-slices
#define JCH   (NPED / NSL) // 512

// Global per-bin counts, [bin][row], accumulated with integer RED.
__device__ unsigned g_cnt[NN * NPED];

// ---------------------------------------------------------------------------
// Zero the count buffer (must precede count_kernel; same stream = ordered).
// ---------------------------------------------------------------------------
__global__ __launch_bounds__(256) void zero_kernel() {
    uint4 z = make_uint4(0u, 0u, 0u, 0u);
    ((uint4*)g_cnt)[blockIdx.x * 256 + threadIdx.x] = z;  // 288 blocks * 256 * 16B
}

// ---------------------------------------------------------------------------
// Phase 1: per-row occupancy histogram over a j-slice. No F2I: floor via
// round-down add of 2^23, bounds via unsigned compare on the mantissa bits.
// ---------------------------------------------------------------------------
__global__ __launch_bounds__(RPB) void count_kernel(const float* __restrict__ obs2) {
    __shared__ unsigned cnt[NN][RPB];   // 18 KB, bin-major: thread t -> bank t%32
    __shared__ float2   pts[JCH];       // 4 KB

    const int t  = threadIdx.x;
    const int i  = blockIdx.x * RPB + t;
    const int j0 = blockIdx.y * JCH;

    // Stage slice points (vectorized: 256 float4 = 512 float2)
    {
        const float4* src = (const float4*)(obs2 + 2 * j0);
        float4* dst = (float4*)pts;
#pragma unroll
        for (int k = 0; k < JCH / 2 / RPB; k++)
            dst[t + k * RPB] = src[t + k * RPB];
    }
#pragma unroll
    for (int c = 0; c < NN; c++) cnt[c][t] = 0u;

    const float2 pi = ((const float2*)obs2)[i];
    __syncthreads();

    const float xi = pi.x, yi = pi.y;
    const float MAGIC = 8388608.0f;     // 2^23

#pragma unroll 8
    for (int k = 0; k < JCH; k++) {
        const float2 pj = pts[k];              // warp-uniform broadcast LDS
        // EXACT reference order: (obs2[j] - obs2[i]) + 3.0f
        const float ex = (pj.x - xi) + 3.0f;
        const float ey = (pj.y - yi) + 3.0f;
        float fx, fy;
        asm("add.rm.f32 %0, %1, %2;" : "=f"(fx) : "f"(ex), "f"(MAGIC));
        asm("add.rm.f32 %0, %1, %2;" : "=f"(fy) : "f"(ey), "f"(MAGIC));
        // bits(2^23 + floor(e)) - bits(2^23) = floor(e); out-of-range -> huge
        const unsigned bx = __float_as_uint(fx) - 0x4B000000u;
        const unsigned by = __float_as_uint(fy) - 0x4B000000u;
        if (umax(bx, by) < 6u)
            cnt[bx * GN + by][t] += 1u;        // conflict-free private counter
    }
    // No sync: each thread only touched its own counter column.

    // Flush: integer RED into global counts (coalesced over i).
#pragma unroll
    for (int c = 0; c < NN; c++) {
        unsigned v = cnt[c][t];
        if (v)
            asm volatile("red.global.add.u32 [%0], %1;"
                         :: "l"(&g_cnt[c * NPED + i]), "r"(v) : "memory");
    }
}

// ---------------------------------------------------------------------------
// Phase 2: read counts, remove self-pair (always bin 21), linear embedding.
// ---------------------------------------------------------------------------
#define P2R 32
__global__ __launch_bounds__(256) void embed_kernel(const float* __restrict__ W,
                                                    const float* __restrict__ b,
                                                    float* __restrict__ out) {
    __shared__ float Ws[NN][HID];   // Ws[c][h] = W[h*NN + c]
    __shared__ float bs[HID];
    __shared__ float cs[P2R][NN];

    const int t  = threadIdx.x;
    const int i0 = blockIdx.x * P2R;

    for (int idx = t; idx < HID * NN; idx += 256)
        Ws[idx % NN][idx / NN] = W[idx];
    if (t < HID) bs[t] = b[t];

    // Load counts: thread -> (c, r), lanes cover consecutive rows (coalesced).
    for (int idx = t; idx < P2R * NN; idx += 256) {
        const int c = idx >> 5;
        const int r = idx & 31;
        unsigned v = g_cnt[c * NPED + i0 + r];
        if (c == 3 * GN + 3) v -= 1u;           // self pair lands in bin (3,3)
        cs[r][c] = (float)v;
    }
    __syncthreads();

    const int h     = t & (HID - 1);
    const int rbase = (t >> 7) * (P2R / 2);

    float w[NN];
#pragma unroll
    for (int c = 0; c < NN; c++) w[c] = Ws[c][h];   // bank = h%32, conflict-free
    const float bh = bs[h];

#pragma unroll
    for (int r = 0; r < P2R / 2; r++) {
        float acc = bh;
#pragma unroll
        for (int c = 0; c < NN; c++)
            acc = fmaf(cs[rbase + r][c], w[c], acc); // warp-uniform broadcast
        out[(i0 + rbase + r) * HID + h] = acc;
    }
}

// ---------------------------------------------------------------------------
// Inputs: 0 hidden_state (unused), 1 obs1 (unused), 2 obs2 [8192,2],
// 3 W [128,36], 4 b [128]. Output fp32 [8192,128].
// ---------------------------------------------------------------------------
extern "C" void kernel_launch(void* const* d_in, const int* in_sizes, int n_in,
                              void* d_out, int out_size) {
    const float* obs2 = (const float*)d_in[2];
    const float* W    = (const float*)d_in[3];
    const float* b    = (const float*)d_in[4];
    float*       out  = (float*)d_out;

    zero_kernel<<<NN * NPED / (256 * 4), 256>>>();
    dim3 g1(NPED / RPB, NSL);                 // 64 x 16 = 1024 blocks
    count_kernel<<<g1, RPB>>>(obs2);
    embed_kernel<<<NPED / P2R, 256>>>(W, b, out);
}